// round 1
// baseline (speedup 1.0000x reference)
#include <cuda_runtime.h>
#include <cstdint>

#define Bn 1024
#define Nn 64
#define Cn 256
#define Hn 8
#define On 64
#define HOn 512

#define XS_STRIDE 260   // multiple of 4 (float4 align), %32==4 (bank spread)
#define TS 68           // tile row stride, multiple of 4, %32==4

typedef unsigned long long ull;

// ---------- f32x2 packed-FMA helpers ----------
__device__ __forceinline__ ull fma2(ull a, ull b, ull c) {
    ull d;
    asm("fma.rn.f32x2 %0, %1, %2, %3;" : "=l"(d) : "l"(a), "l"(b), "l"(c));
    return d;
}
__device__ __forceinline__ ull pack2(float x) {
    ull d;
    asm("mov.b64 %0, {%1, %1};" : "=l"(d) : "f"(x));
    return d;
}
__device__ __forceinline__ float2 unpack2(ull v) {
    float2 r;
    asm("mov.b64 {%0, %1}, %2;" : "=f"(r.x), "=f"(r.y) : "l"(v));
    return r;
}

// ---------- transposed-weight scratch (device globals: no allocation) ----------
__device__ __align__(16) float g_WqT[Cn * HOn];
__device__ __align__(16) float g_WkT[Cn * HOn];
__device__ __align__(16) float g_WvT[Cn * HOn];
__device__ __align__(16) float g_WsT[Cn * On];

__global__ void transpose_weights_kernel(const float* __restrict__ Wq,
                                         const float* __restrict__ Wk,
                                         const float* __restrict__ Wv,
                                         const float* __restrict__ Ws) {
    int idx = blockIdx.x * 256 + threadIdx.x;
    if (idx < Cn * HOn) {
        int c = idx / HOn, ho = idx - c * HOn;
        g_WqT[idx] = Wq[ho * Cn + c];
        g_WkT[idx] = Wk[ho * Cn + c];
        g_WvT[idx] = Wv[ho * Cn + c];
    }
    if (idx < Cn * On) {
        int c = idx / On, o = idx - c * On;
        g_WsT[idx] = Ws[o * Cn + c];
    }
}

// ---------- shared-memory layout (one batch item) ----------
struct __align__(16) Smem {
    float xs[Nn][XS_STRIDE];   // x row-major [i][c]
    float adjs[Nn][Nn + 1];    // adj[b] row-major: adjs[j][i] = adjT[i][j]
    float qT[Nn][TS];          // q transposed [o][i]
    float kT[Nn][TS];          // k transposed [o][j]
    float vs[Nn][TS];          // v row-major [j][o]
    float sc[Nn][TS];          // scores -> alpha -> final output staging
    float qe[Nn];
    float ec[Nn];
    float ewsh[Nn];
    float pad_[4];
};

// GEMM: out tile (4 rows i0..i0+3) x (8 cols as 4 f32x2 pairs), K = Cn.
// xrow = &xs[i0][0] (row stride XS_STRIDE), wcol = transposed weight + col offset,
// row stride WS. All-x loads are LDS.128 (2 distinct addrs/warp -> cheap),
// w loads are 256B-coalesced LDG.128 (L1/L2 resident).
template <int WS>
__device__ __forceinline__ void gemm16(const float* __restrict__ xrow,
                                       const float* __restrict__ wcol,
                                       ull acc[4][2]) {
#pragma unroll
    for (int a = 0; a < 4; a++) { acc[a][0] = 0ull; acc[a][1] = 0ull; }
#pragma unroll 2
    for (int c4 = 0; c4 < Cn / 4; c4++) {
        float4 xv[4];
#pragma unroll
        for (int a = 0; a < 4; a++)
            xv[a] = *reinterpret_cast<const float4*>(xrow + a * XS_STRIDE + c4 * 4);
        ulonglong2 wv[4];
#pragma unroll
        for (int cc = 0; cc < 4; cc++)
            wv[cc] = *reinterpret_cast<const ulonglong2*>(wcol + (c4 * 4 + cc) * WS);
#pragma unroll
        for (int cc = 0; cc < 4; cc++) {
#pragma unroll
            for (int a = 0; a < 4; a++) {
                float xsc = reinterpret_cast<const float*>(&xv[a])[cc];
                ull xp = pack2(xsc);
                acc[a][0] = fma2(xp, wv[cc].x, acc[a][0]);
                acc[a][1] = fma2(xp, wv[cc].y, acc[a][1]);
            }
        }
    }
}

__global__ void __launch_bounds__(256, 1)
graph_attn_kernel(const float* __restrict__ ctx, const float* __restrict__ adj,
                  const float* __restrict__ bq, const float* __restrict__ bk,
                  const float* __restrict__ bv, const float* __restrict__ We,
                  const float* __restrict__ bs, float* __restrict__ outg) {
    extern __shared__ char smem_raw[];
    Smem& s = *reinterpret_cast<Smem*>(smem_raw);

    const int b = blockIdx.x;
    const int tid = (int)threadIdx.x;
    const int ti = tid >> 4, to = tid & 15;
    const int i0 = ti * 4, o0 = to * 4;
    const int warp = tid >> 5, lane = tid & 31;

    // ---- load x (64x256) and adj (64x64) into SMEM ----
    {
        const float4* xg = reinterpret_cast<const float4*>(ctx + (size_t)b * Nn * Cn);
#pragma unroll
        for (int it = 0; it < 16; it++) {
            int p = tid + it * 256;             // 4096 float4
            int i = p >> 6, c4 = p & 63;
            float4 v = xg[p];
            *reinterpret_cast<float4*>(&s.xs[i][c4 * 4]) = v;
        }
        const float4* ag = reinterpret_cast<const float4*>(adj + (size_t)b * Nn * Nn);
#pragma unroll
        for (int it = 0; it < 4; it++) {
            int p = tid + it * 256;             // 1024 float4
            int j = p >> 4, i4 = p & 15;
            float4 v = ag[p];
            float* dst = &s.adjs[j][i4 * 4];    // stride 65: scalar stores
            dst[0] = v.x; dst[1] = v.y; dst[2] = v.z; dst[3] = v.w;
        }
    }
    __syncthreads();

    // ---- skip GEMM: x @ Ws^T (bias added at the end) ----
    ull skipacc[4][2];
    gemm16<On>(&s.xs[i0][0], g_WsT + o0, skipacc);

    // head-sum accumulator (sum over heads of AV + ecoef*ew)
    ull hacc[4][2];
#pragma unroll
    for (int a = 0; a < 4; a++) { hacc[a][0] = 0ull; hacc[a][1] = 0ull; }

    for (int h = 0; h < Hn; h++) {
        ull acc[4][2];

        // ---- Q projection -> qT[o][i] ----
        gemm16<HOn>(&s.xs[i0][0], g_WqT + h * On + o0, acc);
        {
            float4 bqv = *reinterpret_cast<const float4*>(&bq[h * On + o0]);
            const float bb[4] = {bqv.x, bqv.y, bqv.z, bqv.w};
#pragma unroll
            for (int a = 0; a < 4; a++) {
#pragma unroll
                for (int p = 0; p < 2; p++) {
                    float2 r = unpack2(acc[a][p]);
                    s.qT[o0 + 2 * p][i0 + a]     = r.x + bb[2 * p];
                    s.qT[o0 + 2 * p + 1][i0 + a] = r.y + bb[2 * p + 1];
                }
            }
        }

        // ---- K projection -> kT[o][j] ----
        gemm16<HOn>(&s.xs[i0][0], g_WkT + h * On + o0, acc);
        {
            float4 bkv = *reinterpret_cast<const float4*>(&bk[h * On + o0]);
            const float bb[4] = {bkv.x, bkv.y, bkv.z, bkv.w};
#pragma unroll
            for (int a = 0; a < 4; a++) {
#pragma unroll
                for (int p = 0; p < 2; p++) {
                    float2 r = unpack2(acc[a][p]);
                    s.kT[o0 + 2 * p][i0 + a]     = r.x + bb[2 * p];
                    s.kT[o0 + 2 * p + 1][i0 + a] = r.y + bb[2 * p + 1];
                }
            }
        }

        // ---- V projection -> vs[j][o] (row-major) ----
        gemm16<HOn>(&s.xs[i0][0], g_WvT + h * On + o0, acc);
        {
            float4 bvv = *reinterpret_cast<const float4*>(&bv[h * On + o0]);
#pragma unroll
            for (int a = 0; a < 4; a++) {
                float2 r0 = unpack2(acc[a][0]), r1 = unpack2(acc[a][1]);
                float4 res;
                res.x = r0.x + bvv.x; res.y = r0.y + bvv.y;
                res.z = r1.x + bvv.z; res.w = r1.y + bvv.w;
                *reinterpret_cast<float4*>(&s.vs[i0 + a][o0]) = res;
            }
        }
        __syncthreads();  // S1: qT/kT/vs visible

        // ---- qe[i] = q[i,:] . ew ; stage ew for this head ----
        if (tid < Nn) {
            const float* Weh = We + h * On;
            float acce = 0.f;
#pragma unroll 8
            for (int o = 0; o < Nn; o++) acce += s.qT[o][tid] * __ldg(&Weh[o]);
            s.qe[tid] = acce;
            s.ewsh[tid] = __ldg(&Weh[tid]);
        }
        __syncthreads();  // S2

        // ---- scores = (q k^T + adjT * qe) / 8 ----
        {
            ull sacc[4][2];
#pragma unroll
            for (int a = 0; a < 4; a++) { sacc[a][0] = 0ull; sacc[a][1] = 0ull; }
#pragma unroll 4
            for (int o = 0; o < Nn; o++) {
                ulonglong2 kv = *reinterpret_cast<const ulonglong2*>(&s.kT[o][o0]);
#pragma unroll
                for (int a = 0; a < 4; a++) {
                    ull qp = pack2(s.qT[o][i0 + a]);
                    sacc[a][0] = fma2(qp, kv.x, sacc[a][0]);
                    sacc[a][1] = fma2(qp, kv.y, sacc[a][1]);
                }
            }
#pragma unroll
            for (int a = 0; a < 4; a++) {
                int i = i0 + a;
                float qei = s.qe[i];
                float2 r0 = unpack2(sacc[a][0]), r1 = unpack2(sacc[a][1]);
                float4 res;
                res.x = (r0.x + s.adjs[o0 + 0][i] * qei) * 0.125f;
                res.y = (r0.y + s.adjs[o0 + 1][i] * qei) * 0.125f;
                res.z = (r1.x + s.adjs[o0 + 2][i] * qei) * 0.125f;
                res.w = (r1.y + s.adjs[o0 + 3][i] * qei) * 0.125f;
                *reinterpret_cast<float4*>(&s.sc[i][o0]) = res;
            }
        }
        __syncthreads();  // S3

        // ---- softmax over j (each warp owns 8 rows); ecoef = sum alpha*adjT ----
        {
#pragma unroll
            for (int r = 0; r < 8; r++) {
                int row = warp * 8 + r;
                float v0 = s.sc[row][lane], v1 = s.sc[row][lane + 32];
                float m = fmaxf(v0, v1);
#pragma unroll
                for (int d2 = 16; d2 > 0; d2 >>= 1)
                    m = fmaxf(m, __shfl_xor_sync(0xffffffffu, m, d2));
                float e0 = __expf(v0 - m), e1 = __expf(v1 - m);
                float ssum = e0 + e1;
                float ea = e0 * s.adjs[lane][row] + e1 * s.adjs[lane + 32][row];
#pragma unroll
                for (int d2 = 16; d2 > 0; d2 >>= 1) {
                    ssum += __shfl_xor_sync(0xffffffffu, ssum, d2);
                    ea   += __shfl_xor_sync(0xffffffffu, ea, d2);
                }
                float inv = 1.0f / ssum;
                s.sc[row][lane]      = e0 * inv;
                s.sc[row][lane + 32] = e1 * inv;
                if (lane == 0) s.ec[row] = ea * inv;
            }
        }
        __syncthreads();  // S4

        // ---- out_h = alpha @ v + ecoef * ew ; accumulate over heads ----
        {
#pragma unroll 4
            for (int j = 0; j < Nn; j++) {
                ulonglong2 vv = *reinterpret_cast<const ulonglong2*>(&s.vs[j][o0]);
#pragma unroll
                for (int a = 0; a < 4; a++) {
                    ull ap = pack2(s.sc[i0 + a][j]);
                    hacc[a][0] = fma2(ap, vv.x, hacc[a][0]);
                    hacc[a][1] = fma2(ap, vv.y, hacc[a][1]);
                }
            }
            ulonglong2 ewv = *reinterpret_cast<const ulonglong2*>(&s.ewsh[o0]);
#pragma unroll
            for (int a = 0; a < 4; a++) {
                ull ep = pack2(s.ec[i0 + a]);
                hacc[a][0] = fma2(ep, ewv.x, hacc[a][0]);
                hacc[a][1] = fma2(ep, ewv.y, hacc[a][1]);
            }
        }
        __syncthreads();  // S5: protect qT/kT/vs/sc for next head
    }

    // ---- final: mean heads + skip + bias, threshold, sigmoid ----
    {
        float4 bsv = *reinterpret_cast<const float4*>(&bs[o0]);
        const float bb[4] = {bsv.x, bsv.y, bsv.z, bsv.w};
#pragma unroll
        for (int a = 0; a < 4; a++) {
            float2 h0 = unpack2(hacc[a][0]), h1 = unpack2(hacc[a][1]);
            float2 s0 = unpack2(skipacc[a][0]), s1 = unpack2(skipacc[a][1]);
            float z0 = s0.x + h0.x * 0.125f + bb[0];
            float z1 = s0.y + h0.y * 0.125f + bb[1];
            float z2 = s1.x + h1.x * 0.125f + bb[2];
            float z3 = s1.y + h1.y * 0.125f + bb[3];
            float4 res;
            res.x = (z0 > 0.1f) ? 1.0f / (1.0f + __expf(-z0)) : 0.0f;
            res.y = (z1 > 0.1f) ? 1.0f / (1.0f + __expf(-z1)) : 0.0f;
            res.z = (z2 > 0.1f) ? 1.0f / (1.0f + __expf(-z2)) : 0.0f;
            res.w = (z3 > 0.1f) ? 1.0f / (1.0f + __expf(-z3)) : 0.0f;
            *reinterpret_cast<float4*>(&s.sc[i0 + a][o0]) = res;
        }
    }
    __syncthreads();
    {
        float4* og = reinterpret_cast<float4*>(outg + (size_t)b * Nn * On);
#pragma unroll
        for (int it = 0; it < 4; it++) {
            int p = tid + it * 256;             // 1024 float4
            int i = p >> 4, g4 = p & 15;
            og[p] = *reinterpret_cast<const float4*>(&s.sc[i][g4 * 4]);
        }
    }
}

extern "C" void kernel_launch(void* const* d_in, const int* in_sizes, int n_in,
                              void* d_out, int out_size) {
    (void)in_sizes; (void)n_in; (void)out_size;
    const float* ctx = (const float*)d_in[0];
    const float* adj = (const float*)d_in[1];
    const float* Wq  = (const float*)d_in[2];
    const float* bq  = (const float*)d_in[3];
    const float* Wk  = (const float*)d_in[4];
    const float* bk  = (const float*)d_in[5];
    const float* Wv  = (const float*)d_in[6];
    const float* bv  = (const float*)d_in[7];
    const float* We  = (const float*)d_in[8];
    const float* Ws  = (const float*)d_in[9];
    const float* bs  = (const float*)d_in[10];
    float* outg = (float*)d_out;

    transpose_weights_kernel<<<(Cn * HOn + 255) / 256, 256>>>(Wq, Wk, Wv, Ws);

    static int attr_set = 0;
    // cudaFuncSetAttribute is idempotent and not a stream op; safe every call.
    cudaFuncSetAttribute(graph_attn_kernel,
                         cudaFuncAttributeMaxDynamicSharedMemorySize,
                         (int)sizeof(Smem));
    (void)attr_set;

    graph_attn_kernel<<<Bn, 256, sizeof(Smem)>>>(ctx, adj, bq, bk, bv, We, bs, outg);
}

// round 3
// speedup vs baseline: 1.1427x; 1.1427x over previous
#include <cuda_runtime.h>
#include <cstdint>

#define Bn 1024
#define Nn 64
#define Cn 256
#define Hn 8
#define On 64
#define HOn 512

#define THREADS 384
#define XS_STRIDE 260   // multiple of 4 (float4 align), %32==4 (bank spread)
#define TS 68           // tile row stride, multiple of 4, %32==4

typedef unsigned long long ull;

// ---------- f32x2 packed-FMA helpers ----------
__device__ __forceinline__ ull fma2(ull a, ull b, ull c) {
    ull d;
    asm("fma.rn.f32x2 %0, %1, %2, %3;" : "=l"(d) : "l"(a), "l"(b), "l"(c));
    return d;
}
__device__ __forceinline__ ull pack2(float x) {
    ull d;
    asm("mov.b64 %0, {%1, %1};" : "=l"(d) : "f"(x));
    return d;
}
__device__ __forceinline__ float2 unpack2(ull v) {
    float2 r;
    asm("mov.b64 {%0, %1}, %2;" : "=f"(r.x), "=f"(r.y) : "l"(v));
    return r;
}

// ---------- transposed-weight scratch (device globals: no allocation) ----------
__device__ __align__(16) float g_WqT[Cn * HOn];
__device__ __align__(16) float g_WkT[Cn * HOn];
__device__ __align__(16) float g_WvT[Cn * HOn];
__device__ __align__(16) float g_WsT[Cn * On];

__global__ void transpose_weights_kernel(const float* __restrict__ Wq,
                                         const float* __restrict__ Wk,
                                         const float* __restrict__ Wv,
                                         const float* __restrict__ Ws) {
    int idx = blockIdx.x * 256 + threadIdx.x;
    if (idx < Cn * HOn) {
        int c = idx / HOn, ho = idx - c * HOn;
        g_WqT[idx] = Wq[ho * Cn + c];
        g_WkT[idx] = Wk[ho * Cn + c];
        g_WvT[idx] = Wv[ho * Cn + c];
    }
    if (idx < Cn * On) {
        int c = idx / On, o = idx - c * On;
        g_WsT[idx] = Ws[o * Cn + c];
    }
}

// ---------- shared-memory layout (one batch item) ----------
struct __align__(16) Smem {
    float xs[Nn][XS_STRIDE];   // x row-major [i][c]
    float adjs[Nn][Nn + 1];    // adj[b] row-major: adjs[j][i] = adjT[i][j]
    float qs[Nn][TS];          // q row-major [i][o]
    float kT[Nn][TS];          // k transposed [o][j]
    float vs[Nn][TS];          // v row-major [j][o]
    float sc[Nn][TS];          // scores -> alpha -> final output staging
    float skips[Nn][TS];       // x @ Ws^T (no bias)
    float qe[Nn];
    float ec[Nn];
    float ewsh[Nn];
    float pad_[4];
};

// GEMM: out tile 4 rows (pi0..pi0+3) x 8 cols (4 f32x2 pairs), K = Cn.
// 128 threads per group cover 64x64. x loads: LDS.128 broadcast.
// w loads: per-warp one 128B line (8 distinct 16B + broadcast).
template <int WS>
__device__ __forceinline__ void gemm48(const float* __restrict__ xrow,
                                       const float* __restrict__ wcol,
                                       ull acc[4][4]) {
#pragma unroll
    for (int a = 0; a < 4; a++)
#pragma unroll
        for (int u = 0; u < 4; u++) acc[a][u] = 0ull;
#pragma unroll 2
    for (int c4 = 0; c4 < Cn / 4; c4++) {
        float4 xv[4];
#pragma unroll
        for (int a = 0; a < 4; a++)
            xv[a] = *reinterpret_cast<const float4*>(xrow + a * XS_STRIDE + c4 * 4);
        ulonglong2 wv[4][2];
#pragma unroll
        for (int cc = 0; cc < 4; cc++) {
            const float* wp = wcol + (c4 * 4 + cc) * WS;
            wv[cc][0] = *reinterpret_cast<const ulonglong2*>(wp);
            wv[cc][1] = *reinterpret_cast<const ulonglong2*>(wp + 4);
        }
#pragma unroll
        for (int cc = 0; cc < 4; cc++) {
#pragma unroll
            for (int a = 0; a < 4; a++) {
                float xsc = reinterpret_cast<const float*>(&xv[a])[cc];
                ull xp = pack2(xsc);
                acc[a][0] = fma2(xp, wv[cc][0].x, acc[a][0]);
                acc[a][1] = fma2(xp, wv[cc][0].y, acc[a][1]);
                acc[a][2] = fma2(xp, wv[cc][1].x, acc[a][2]);
                acc[a][3] = fma2(xp, wv[cc][1].y, acc[a][3]);
            }
        }
    }
}

__global__ void __launch_bounds__(THREADS, 1)
graph_attn_kernel(const float* __restrict__ ctx, const float* __restrict__ adj,
                  const float* __restrict__ bq, const float* __restrict__ bk,
                  const float* __restrict__ bv, const float* __restrict__ We,
                  const float* __restrict__ bs, float* __restrict__ outg) {
    extern __shared__ char smem_raw[];
    Smem& s = *reinterpret_cast<Smem*>(smem_raw);

    const int b = blockIdx.x;
    const int tid = (int)threadIdx.x;
    // projection mapping: 3 groups of 128 threads, 4 rows x 8 cols per thread
    const int g = tid >> 7;               // 0=Q, 1=K, 2=V(+skip)
    const int wg = tid & 127;
    const int pi0 = (wg >> 3) * 4;        // row base
    const int po0 = (wg & 7) * 8;         // col base (8 wide)
    // attention mapping (tid < 256): 4 rows x 4 cols per thread
    const int ti = tid >> 4, to = tid & 15;
    const int i0 = ti * 4, o0 = to * 4;
    const int warp = tid >> 5, lane = tid & 31;

    // ---- load x (64x256) and adj (64x64) into SMEM ----
    {
        const float4* xg = reinterpret_cast<const float4*>(ctx + (size_t)b * Nn * Cn);
        for (int p = tid; p < 4096; p += THREADS) {
            int i = p >> 6, c4 = p & 63;
            *reinterpret_cast<float4*>(&s.xs[i][c4 * 4]) = xg[p];
        }
        const float4* ag = reinterpret_cast<const float4*>(adj + (size_t)b * Nn * Nn);
        for (int p = tid; p < 1024; p += THREADS) {
            int j = p >> 4, i4 = p & 15;
            float4 v = ag[p];
            float* dst = &s.adjs[j][i4 * 4];    // stride 65: scalar stores
            dst[0] = v.x; dst[1] = v.y; dst[2] = v.z; dst[3] = v.w;
        }
    }
    __syncthreads();

    // ---- skip GEMM: x @ Ws^T -> smem (group 2 only, once) ----
    if (g == 2) {
        ull sk[4][4];
        gemm48<On>(&s.xs[pi0][0], g_WsT + po0, sk);
#pragma unroll
        for (int a = 0; a < 4; a++) {
            float2 r0 = unpack2(sk[a][0]), r1 = unpack2(sk[a][1]);
            float2 r2 = unpack2(sk[a][2]), r3 = unpack2(sk[a][3]);
            float4 v0 = {r0.x, r0.y, r1.x, r1.y};
            float4 v1 = {r2.x, r2.y, r3.x, r3.y};
            *reinterpret_cast<float4*>(&s.skips[pi0 + a][po0]) = v0;
            *reinterpret_cast<float4*>(&s.skips[pi0 + a][po0 + 4]) = v1;
        }
    }

    // head-sum accumulator (sum over heads of AV + ecoef*ew) — tid<256 mapping
    ull hacc[4][2];
#pragma unroll
    for (int a = 0; a < 4; a++) { hacc[a][0] = 0ull; hacc[a][1] = 0ull; }

    for (int h = 0; h < Hn; h++) {
        const float* Weh = We + h * On;

        if (g == 0) {
            // ---- Q projection -> qs row-major; fused partial qe ----
            ull acc[4][4];
            gemm48<HOn>(&s.xs[pi0][0], g_WqT + h * On + po0, acc);
            float4 b0 = *reinterpret_cast<const float4*>(&bq[h * On + po0]);
            float4 b1 = *reinterpret_cast<const float4*>(&bq[h * On + po0 + 4]);
            float4 e0 = *reinterpret_cast<const float4*>(&Weh[po0]);
            float4 e1 = *reinterpret_cast<const float4*>(&Weh[po0 + 4]);
#pragma unroll
            for (int a = 0; a < 4; a++) {
                float2 r0 = unpack2(acc[a][0]), r1 = unpack2(acc[a][1]);
                float2 r2 = unpack2(acc[a][2]), r3 = unpack2(acc[a][3]);
                float4 q0 = {r0.x + b0.x, r0.y + b0.y, r1.x + b0.z, r1.y + b0.w};
                float4 q1 = {r2.x + b1.x, r2.y + b1.y, r3.x + b1.z, r3.y + b1.w};
                *reinterpret_cast<float4*>(&s.qs[pi0 + a][po0]) = q0;
                *reinterpret_cast<float4*>(&s.qs[pi0 + a][po0 + 4]) = q1;
                float pe = q0.x * e0.x + q0.y * e0.y + q0.z * e0.z + q0.w * e0.w
                         + q1.x * e1.x + q1.y * e1.y + q1.z * e1.z + q1.w * e1.w;
#pragma unroll
                for (int d = 4; d > 0; d >>= 1)
                    pe += __shfl_xor_sync(0xffffffffu, pe, d);
                if ((wg & 7) == 0) s.qe[pi0 + a] = pe;
            }
        } else if (g == 1) {
            // ---- K projection -> kT transposed ----
            ull acc[4][4];
            gemm48<HOn>(&s.xs[pi0][0], g_WkT + h * On + po0, acc);
            float4 b0 = *reinterpret_cast<const float4*>(&bk[h * On + po0]);
            float4 b1 = *reinterpret_cast<const float4*>(&bk[h * On + po0 + 4]);
            const float bb[8] = {b0.x, b0.y, b0.z, b0.w, b1.x, b1.y, b1.z, b1.w};
#pragma unroll
            for (int a = 0; a < 4; a++) {
                float v[8];
                float2 r0 = unpack2(acc[a][0]), r1 = unpack2(acc[a][1]);
                float2 r2 = unpack2(acc[a][2]), r3 = unpack2(acc[a][3]);
                v[0] = r0.x; v[1] = r0.y; v[2] = r1.x; v[3] = r1.y;
                v[4] = r2.x; v[5] = r2.y; v[6] = r3.x; v[7] = r3.y;
#pragma unroll
                for (int c = 0; c < 8; c++)
                    s.kT[po0 + c][pi0 + a] = v[c] + bb[c];
            }
        } else {
            // ---- V projection -> vs row-major; stage ewsh ----
            ull acc[4][4];
            gemm48<HOn>(&s.xs[pi0][0], g_WvT + h * On + po0, acc);
            float4 b0 = *reinterpret_cast<const float4*>(&bv[h * On + po0]);
            float4 b1 = *reinterpret_cast<const float4*>(&bv[h * On + po0 + 4]);
#pragma unroll
            for (int a = 0; a < 4; a++) {
                float2 r0 = unpack2(acc[a][0]), r1 = unpack2(acc[a][1]);
                float2 r2 = unpack2(acc[a][2]), r3 = unpack2(acc[a][3]);
                float4 v0 = {r0.x + b0.x, r0.y + b0.y, r1.x + b0.z, r1.y + b0.w};
                float4 v1 = {r2.x + b1.x, r2.y + b1.y, r3.x + b1.z, r3.y + b1.w};
                *reinterpret_cast<float4*>(&s.vs[pi0 + a][po0]) = v0;
                *reinterpret_cast<float4*>(&s.vs[pi0 + a][po0 + 4]) = v1;
            }
            if (wg < Nn) s.ewsh[wg] = Weh[wg];
        }
        __syncthreads();  // S1: qs/kT/vs/qe/ewsh visible

        // ---- scores = (q k^T + adjT * qe) / 8  (tid < 256, 4x4 tiles) ----
        if (tid < 256) {
            ull sacc[4][2];
#pragma unroll
            for (int a = 0; a < 4; a++) { sacc[a][0] = 0ull; sacc[a][1] = 0ull; }
#pragma unroll 4
            for (int o = 0; o < Nn; o++) {
                ulonglong2 kv = *reinterpret_cast<const ulonglong2*>(&s.kT[o][o0]);
#pragma unroll
                for (int a = 0; a < 4; a++) {
                    ull qp = pack2(s.qs[i0 + a][o]);
                    sacc[a][0] = fma2(qp, kv.x, sacc[a][0]);
                    sacc[a][1] = fma2(qp, kv.y, sacc[a][1]);
                }
            }
#pragma unroll
            for (int a = 0; a < 4; a++) {
                int i = i0 + a;
                float qei = s.qe[i];
                float2 r0 = unpack2(sacc[a][0]), r1 = unpack2(sacc[a][1]);
                float4 res;
                res.x = (r0.x + s.adjs[o0 + 0][i] * qei) * 0.125f;
                res.y = (r0.y + s.adjs[o0 + 1][i] * qei) * 0.125f;
                res.z = (r1.x + s.adjs[o0 + 2][i] * qei) * 0.125f;
                res.w = (r1.y + s.adjs[o0 + 3][i] * qei) * 0.125f;
                *reinterpret_cast<float4*>(&s.sc[i][o0]) = res;
            }
        }
        __syncthreads();  // S3

        // ---- softmax over j (warps 0-7 own 8 rows each) ----
        if (warp < 8) {
#pragma unroll
            for (int r = 0; r < 8; r++) {
                int row = warp * 8 + r;
                float v0 = s.sc[row][lane], v1 = s.sc[row][lane + 32];
                float m = fmaxf(v0, v1);
#pragma unroll
                for (int d2 = 16; d2 > 0; d2 >>= 1)
                    m = fmaxf(m, __shfl_xor_sync(0xffffffffu, m, d2));
                float e0 = __expf(v0 - m), e1 = __expf(v1 - m);
                float ssum = e0 + e1;
                float ea = e0 * s.adjs[lane][row] + e1 * s.adjs[lane + 32][row];
#pragma unroll
                for (int d2 = 16; d2 > 0; d2 >>= 1) {
                    ssum += __shfl_xor_sync(0xffffffffu, ssum, d2);
                    ea   += __shfl_xor_sync(0xffffffffu, ea, d2);
                }
                float inv = 1.0f / ssum;
                s.sc[row][lane]      = e0 * inv;
                s.sc[row][lane + 32] = e1 * inv;
                if (lane == 0) s.ec[row] = ea * inv;
            }
        }
        __syncthreads();  // S4

        // ---- out_h = alpha @ v + ecoef * ew ; accumulate over heads ----
        if (tid < 256) {
#pragma unroll 4
            for (int j = 0; j < Nn; j++) {
                ulonglong2 vv = *reinterpret_cast<const ulonglong2*>(&s.vs[j][o0]);
#pragma unroll
                for (int a = 0; a < 4; a++) {
                    ull ap = pack2(s.sc[i0 + a][j]);
                    hacc[a][0] = fma2(ap, vv.x, hacc[a][0]);
                    hacc[a][1] = fma2(ap, vv.y, hacc[a][1]);
                }
            }
            ulonglong2 ewv = *reinterpret_cast<const ulonglong2*>(&s.ewsh[o0]);
#pragma unroll
            for (int a = 0; a < 4; a++) {
                ull ep = pack2(s.ec[i0 + a]);
                hacc[a][0] = fma2(ep, ewv.x, hacc[a][0]);
                hacc[a][1] = fma2(ep, ewv.y, hacc[a][1]);
            }
        }
        __syncthreads();  // S5: protect buffers for next head
    }

    // ---- final: mean heads + skip + bias, threshold, sigmoid ----
    if (tid < 256) {
        float4 bsv = *reinterpret_cast<const float4*>(&bs[o0]);
        const float bb[4] = {bsv.x, bsv.y, bsv.z, bsv.w};
#pragma unroll
        for (int a = 0; a < 4; a++) {
            float4 sk = *reinterpret_cast<const float4*>(&s.skips[i0 + a][o0]);
            float2 h0 = unpack2(hacc[a][0]), h1 = unpack2(hacc[a][1]);
            float z0 = sk.x + h0.x * 0.125f + bb[0];
            float z1 = sk.y + h0.y * 0.125f + bb[1];
            float z2 = sk.z + h1.x * 0.125f + bb[2];
            float z3 = sk.w + h1.y * 0.125f + bb[3];
            float4 res;
            res.x = (z0 > 0.1f) ? 1.0f / (1.0f + __expf(-z0)) : 0.0f;
            res.y = (z1 > 0.1f) ? 1.0f / (1.0f + __expf(-z1)) : 0.0f;
            res.z = (z2 > 0.1f) ? 1.0f / (1.0f + __expf(-z2)) : 0.0f;
            res.w = (z3 > 0.1f) ? 1.0f / (1.0f + __expf(-z3)) : 0.0f;
            *reinterpret_cast<float4*>(&s.sc[i0 + a][o0]) = res;
        }
    }
    __syncthreads();
    {
        float4* og = reinterpret_cast<float4*>(outg + (size_t)b * Nn * On);
        for (int p = tid; p < 1024; p += THREADS) {
            int i = p >> 4, g4 = p & 15;
            og[p] = *reinterpret_cast<const float4*>(&s.sc[i][g4 * 4]);
        }
    }
}

extern "C" void kernel_launch(void* const* d_in, const int* in_sizes, int n_in,
                              void* d_out, int out_size) {
    (void)in_sizes; (void)n_in; (void)out_size;
    const float* ctx = (const float*)d_in[0];
    const float* adj = (const float*)d_in[1];
    const float* Wq  = (const float*)d_in[2];
    const float* bq  = (const float*)d_in[3];
    const float* Wk  = (const float*)d_in[4];
    const float* bk  = (const float*)d_in[5];
    const float* Wv  = (const float*)d_in[6];
    const float* bv  = (const float*)d_in[7];
    const float* We  = (const float*)d_in[8];
    const float* Ws  = (const float*)d_in[9];
    const float* bs  = (const float*)d_in[10];
    float* outg = (float*)d_out;

    transpose_weights_kernel<<<(Cn * HOn + 255) / 256, 256>>>(Wq, Wk, Wv, Ws);

    cudaFuncSetAttribute(graph_attn_kernel,
                         cudaFuncAttributeMaxDynamicSharedMemorySize,
                         (int)sizeof(Smem));

    graph_attn_kernel<<<Bn, THREADS, sizeof(Smem)>>>(ctx, adj, bq, bk, bv, We, bs, outg);
}

// round 5
// speedup vs baseline: 1.5851x; 1.3872x over previous
#include <cuda_runtime.h>
#include <cstdint>

#define Bn 1024
#define Nn 64
#define Cn 256
#define Hn 8
#define On 64
#define HOn 512

#define THREADS 384
#define XS_STRIDE 260   // multiple of 4 (float4 align)
#define TS 68           // tile row stride, multiple of 4
#define CHUNK_K 32
#define NCHUNK (Cn / CHUNK_K)

typedef unsigned long long ull;

// ---------- f32x2 packed-FMA helpers ----------
__device__ __forceinline__ ull fma2(ull a, ull b, ull c) {
    ull d;
    asm("fma.rn.f32x2 %0, %1, %2, %3;" : "=l"(d) : "l"(a), "l"(b), "l"(c));
    return d;
}
__device__ __forceinline__ ull pack2(float x) {
    ull d;
    asm("mov.b64 %0, {%1, %1};" : "=l"(d) : "f"(x));
    return d;
}
__device__ __forceinline__ float2 unpack2(ull v) {
    float2 r;
    asm("mov.b64 {%0, %1}, %2;" : "=f"(r.x), "=f"(r.y) : "l"(v));
    return r;
}

// ---------- transposed-weight scratch (device globals: no allocation) ----------
__device__ __align__(16) float g_WqT[Cn * HOn];
__device__ __align__(16) float g_WkT[Cn * HOn];
__device__ __align__(16) float g_WvT[Cn * HOn];
__device__ __align__(16) float g_WsT[Cn * On];

__global__ void transpose_weights_kernel(const float* __restrict__ Wq,
                                         const float* __restrict__ Wk,
                                         const float* __restrict__ Wv,
                                         const float* __restrict__ Ws) {
    int idx = blockIdx.x * 256 + threadIdx.x;
    if (idx < Cn * HOn) {
        int c = idx / HOn, ho = idx - c * HOn;
        g_WqT[idx] = Wq[ho * Cn + c];
        g_WkT[idx] = Wk[ho * Cn + c];
        g_WvT[idx] = Wv[ho * Cn + c];
    }
    if (idx < Cn * On) {
        int c = idx / On, o = idx - c * On;
        g_WsT[idx] = Ws[o * Cn + c];
    }
}

// ---------- shared-memory layout (one batch item) ----------
struct __align__(16) Smem {
    float xs[Nn][XS_STRIDE];        // x row-major [i][c]
    float adjs[Nn][Nn + 1];         // adjs[j][i] = adjT[i][j]
    float qs[Nn][TS];               // q row-major [i][o]
    float kT[Nn][TS];               // k transposed [o][j]
    float vs[Nn][TS];               // v row-major [j][o]
    float sc[Nn][TS];               // scores -> alpha -> output staging
    float skips[Nn][TS];            // x @ Ws^T (no bias)
    float wbuf[2][3][CHUNK_K][On];  // double-buffered staged weights (Q,K,V)
    float qe[Nn];
    float ec[Nn];
    float ewsh[Nn];
    float pad_[4];
};

__device__ __forceinline__ uint32_t smem_addr_of(const void* p) {
    uint32_t a;
    asm("{ .reg .u64 t; cvta.to.shared.u64 t, %1; cvt.u32.u64 %0, t; }"
        : "=r"(a) : "l"(p));
    return a;
}

// Stage one K-chunk of Wq/Wk/Wv (head h) into wbuf[buf] via cp.async.
// 3*32*64 floats = 1536 x 16B; 384 threads x 4 chunks.
__device__ __forceinline__ void stage_chunk(Smem& s, int buf, int h, int kc, int tid) {
    const int c0 = kc * CHUNK_K;
#pragma unroll
    for (int i = 0; i < 4; i++) {
        int p = tid + i * THREADS;
        int m = p >> 9;            // matrix 0..2
        int rem = p & 511;
        int kl = rem >> 4, c4 = rem & 15;
        const float* srcbase = (m == 0) ? g_WqT : (m == 1) ? g_WkT : g_WvT;
        const float* src = srcbase + (size_t)(c0 + kl) * HOn + h * On + c4 * 4;
        uint32_t sa = smem_addr_of(&s.wbuf[buf][m][kl][c4 * 4]);
        asm volatile("cp.async.cg.shared.global [%0], [%1], 16;" :: "r"(sa), "l"(src));
    }
    asm volatile("cp.async.commit_group;");
}
#define CP_WAIT0() asm volatile("cp.async.wait_group 0;" ::: "memory")

// Skip GEMM helper: 4 rows x 8 cols tile, weights via LDG (once per CTA).
template <int WS>
__device__ __forceinline__ void gemm48(const float* __restrict__ xrow,
                                       const float* __restrict__ wcol,
                                       ull acc[4][4]) {
#pragma unroll
    for (int a = 0; a < 4; a++)
#pragma unroll
        for (int u = 0; u < 4; u++) acc[a][u] = 0ull;
#pragma unroll 2
    for (int c4 = 0; c4 < Cn / 4; c4++) {
        float4 xv[4];
#pragma unroll
        for (int a = 0; a < 4; a++)
            xv[a] = *reinterpret_cast<const float4*>(xrow + a * XS_STRIDE + c4 * 4);
        ulonglong2 wv[4][2];
#pragma unroll
        for (int cc = 0; cc < 4; cc++) {
            const float* wp = wcol + (c4 * 4 + cc) * WS;
            wv[cc][0] = *reinterpret_cast<const ulonglong2*>(wp);
            wv[cc][1] = *reinterpret_cast<const ulonglong2*>(wp + 4);
        }
#pragma unroll
        for (int cc = 0; cc < 4; cc++) {
#pragma unroll
            for (int a = 0; a < 4; a++) {
                ull xp = pack2(reinterpret_cast<const float*>(&xv[a])[cc]);
                acc[a][0] = fma2(xp, wv[cc][0].x, acc[a][0]);
                acc[a][1] = fma2(xp, wv[cc][0].y, acc[a][1]);
                acc[a][2] = fma2(xp, wv[cc][1].x, acc[a][2]);
                acc[a][3] = fma2(xp, wv[cc][1].y, acc[a][3]);
            }
        }
    }
}

__global__ void __launch_bounds__(THREADS, 1)
graph_attn_kernel(const float* __restrict__ ctx, const float* __restrict__ adj,
                  const float* __restrict__ bq, const float* __restrict__ bk,
                  const float* __restrict__ bv, const float* __restrict__ We,
                  const float* __restrict__ bs, float* __restrict__ outg) {
    extern __shared__ char smem_raw[];
    Smem& s = *reinterpret_cast<Smem*>(smem_raw);

    const int b = blockIdx.x;
    const int tid = (int)threadIdx.x;
    // projection mapping: 3 groups of 128 threads; per-thread tile = 8 rows x 4 cols.
    // rows are rg, rg+8, ..., rg+56 (strided by 8 -> conflict-free x loads)
    const int g = tid >> 7;               // 0=Q, 1=K, 2=V
    const int wg = tid & 127;
    const int rg = wg >> 4;               // row offset 0..7
    const int co0 = (wg & 15) * 4;        // col base (4 wide)
    // skip mapping (old 4x8 on group 2)
    const int pi0s = (wg >> 3) * 4, po0s = (wg & 7) * 8;
    // attention mapping (tid < 256): 4 rows x 4 cols per thread
    const int ti = tid >> 4, to = tid & 15;
    const int i0 = ti * 4, o0 = to * 4;
    const int warp = tid >> 5, lane = tid & 31;

    // prefetch head-0 chunk-0 weights early
    stage_chunk(s, 0, 0, 0, tid);

    // ---- load x (64x256) and adj (64x64) into SMEM ----
    {
        const float4* xg = reinterpret_cast<const float4*>(ctx + (size_t)b * Nn * Cn);
        for (int p = tid; p < 4096; p += THREADS) {
            int i = p >> 6, c4 = p & 63;
            *reinterpret_cast<float4*>(&s.xs[i][c4 * 4]) = xg[p];
        }
        const float4* ag = reinterpret_cast<const float4*>(adj + (size_t)b * Nn * Nn);
        for (int p = tid; p < 1024; p += THREADS) {
            int j = p >> 4, i4 = p & 15;
            float4 v = ag[p];
            float* dst = &s.adjs[j][i4 * 4];
            dst[0] = v.x; dst[1] = v.y; dst[2] = v.z; dst[3] = v.w;
        }
    }
    __syncthreads();

    // ---- skip GEMM: x @ Ws^T -> smem (group 2 only, once) ----
    if (g == 2) {
        ull sk[4][4];
        gemm48<On>(&s.xs[pi0s][0], g_WsT + po0s, sk);
#pragma unroll
        for (int a = 0; a < 4; a++) {
            float2 r0 = unpack2(sk[a][0]), r1 = unpack2(sk[a][1]);
            float2 r2 = unpack2(sk[a][2]), r3 = unpack2(sk[a][3]);
            float4 v0 = {r0.x, r0.y, r1.x, r1.y};
            float4 v1 = {r2.x, r2.y, r3.x, r3.y};
            *reinterpret_cast<float4*>(&s.skips[pi0s + a][po0s]) = v0;
            *reinterpret_cast<float4*>(&s.skips[pi0s + a][po0s + 4]) = v1;
        }
    }
    CP_WAIT0();
    __syncthreads();   // chunk 0 of head 0 staged & visible

    // head-sum accumulator (tid<256 mapping)
    ull hacc[4][2];
#pragma unroll
    for (int a = 0; a < 4; a++) { hacc[a][0] = 0ull; hacc[a][1] = 0ull; }

    for (int h = 0; h < Hn; h++) {
        const float* Weh = We + h * On;

        // ---- projection mainloop: 8 chunks, double buffered ----
        ull acc[8][2];
#pragma unroll
        for (int r = 0; r < 8; r++) { acc[r][0] = 0ull; acc[r][1] = 0ull; }

        for (int kc = 0; kc < NCHUNK; kc++) {
            if (kc < NCHUNK - 1)       stage_chunk(s, (kc + 1) & 1, h, kc + 1, tid);
            else if (h < Hn - 1)       stage_chunk(s, 0, h + 1, 0, tid);

            const float* wb = &s.wbuf[kc & 1][g][0][co0];
            const float* xb = &s.xs[rg][kc * CHUNK_K];
#pragma unroll
            for (int c4 = 0; c4 < CHUNK_K / 4; c4++) {
                float4 xv[8];
#pragma unroll
                for (int r = 0; r < 8; r++)
                    xv[r] = *reinterpret_cast<const float4*>(xb + r * 8 * XS_STRIDE + c4 * 4);
                ulonglong2 wv[4];
#pragma unroll
                for (int cc = 0; cc < 4; cc++)
                    wv[cc] = *reinterpret_cast<const ulonglong2*>(wb + (c4 * 4 + cc) * On);
#pragma unroll
                for (int cc = 0; cc < 4; cc++) {
#pragma unroll
                    for (int r = 0; r < 8; r++) {
                        ull xp = pack2(reinterpret_cast<const float*>(&xv[r])[cc]);
                        acc[r][0] = fma2(xp, wv[cc].x, acc[r][0]);
                        acc[r][1] = fma2(xp, wv[cc].y, acc[r][1]);
                    }
                }
            }
            CP_WAIT0();
            __syncthreads();
        }

        // ---- epilogues per group ----
        if (g == 0) {
            float4 b4 = *reinterpret_cast<const float4*>(&bq[h * On + co0]);
            float4 e4 = *reinterpret_cast<const float4*>(&Weh[co0]);
#pragma unroll
            for (int r = 0; r < 8; r++) {
                int row = rg + 8 * r;
                float2 r0 = unpack2(acc[r][0]), r1 = unpack2(acc[r][1]);
                float4 q = {r0.x + b4.x, r0.y + b4.y, r1.x + b4.z, r1.y + b4.w};
                *reinterpret_cast<float4*>(&s.qs[row][co0]) = q;
                float pe = q.x * e4.x + q.y * e4.y + q.z * e4.z + q.w * e4.w;
#pragma unroll
                for (int d = 8; d > 0; d >>= 1)
                    pe += __shfl_xor_sync(0xffffffffu, pe, d);
                if ((wg & 15) == 0) s.qe[row] = pe;
            }
        } else if (g == 1) {
            float4 b4 = *reinterpret_cast<const float4*>(&bk[h * On + co0]);
            const float bb[4] = {b4.x, b4.y, b4.z, b4.w};
#pragma unroll
            for (int r = 0; r < 8; r++) {
                int row = rg + 8 * r;
                float v[4];
                float2 r0 = unpack2(acc[r][0]), r1 = unpack2(acc[r][1]);
                v[0] = r0.x; v[1] = r0.y; v[2] = r1.x; v[3] = r1.y;
#pragma unroll
                for (int cc = 0; cc < 4; cc++)
                    s.kT[co0 + cc][row] = v[cc] + bb[cc];
            }
        } else {
            float4 b4 = *reinterpret_cast<const float4*>(&bv[h * On + co0]);
#pragma unroll
            for (int r = 0; r < 8; r++) {
                int row = rg + 8 * r;
                float2 r0 = unpack2(acc[r][0]), r1 = unpack2(acc[r][1]);
                float4 v = {r0.x + b4.x, r0.y + b4.y, r1.x + b4.z, r1.y + b4.w};
                *reinterpret_cast<float4*>(&s.vs[row][co0]) = v;
            }
            if (wg < Nn) s.ewsh[wg] = Weh[wg];
        }
        __syncthreads();  // S1: qs/kT/vs/qe/ewsh visible

        // ---- scores = (q k^T + adjT * qe) / 8  (tid < 256, 4x4 tiles) ----
        if (tid < 256) {
            ull sacc[4][2];
#pragma unroll
            for (int a = 0; a < 4; a++) { sacc[a][0] = 0ull; sacc[a][1] = 0ull; }
#pragma unroll 4
            for (int o = 0; o < Nn; o++) {
                ulonglong2 kv = *reinterpret_cast<const ulonglong2*>(&s.kT[o][o0]);
#pragma unroll
                for (int a = 0; a < 4; a++) {
                    ull qp = pack2(s.qs[i0 + a][o]);
                    sacc[a][0] = fma2(qp, kv.x, sacc[a][0]);
                    sacc[a][1] = fma2(qp, kv.y, sacc[a][1]);
                }
            }
#pragma unroll
            for (int a = 0; a < 4; a++) {
                int i = i0 + a;
                float qei = s.qe[i];
                float2 r0 = unpack2(sacc[a][0]), r1 = unpack2(sacc[a][1]);
                float4 res;
                res.x = (r0.x + s.adjs[o0 + 0][i] * qei) * 0.125f;
                res.y = (r0.y + s.adjs[o0 + 1][i] * qei) * 0.125f;
                res.z = (r1.x + s.adjs[o0 + 2][i] * qei) * 0.125f;
                res.w = (r1.y + s.adjs[o0 + 3][i] * qei) * 0.125f;
                *reinterpret_cast<float4*>(&s.sc[i][o0]) = res;
            }
        }
        __syncthreads();

        // ---- softmax over j (warps 0-7 own 8 rows each) ----
        if (warp < 8) {
#pragma unroll
            for (int r = 0; r < 8; r++) {
                int row = warp * 8 + r;
                float v0 = s.sc[row][lane], v1 = s.sc[row][lane + 32];
                float m = fmaxf(v0, v1);
#pragma unroll
                for (int d2 = 16; d2 > 0; d2 >>= 1)
                    m = fmaxf(m, __shfl_xor_sync(0xffffffffu, m, d2));
                float e0 = __expf(v0 - m), e1 = __expf(v1 - m);
                float ssum = e0 + e1;
                float ea = e0 * s.adjs[lane][row] + e1 * s.adjs[lane + 32][row];
#pragma unroll
                for (int d2 = 16; d2 > 0; d2 >>= 1) {
                    ssum += __shfl_xor_sync(0xffffffffu, ssum, d2);
                    ea   += __shfl_xor_sync(0xffffffffu, ea, d2);
                }
                float inv = 1.0f / ssum;
                s.sc[row][lane]      = e0 * inv;
                s.sc[row][lane + 32] = e1 * inv;
                if (lane == 0) s.ec[row] = ea * inv;
            }
        }
        __syncthreads();

        // ---- out_h = alpha @ v + ecoef * ew ; accumulate over heads ----
        if (tid < 256) {
#pragma unroll 4
            for (int j = 0; j < Nn; j++) {
                ulonglong2 vv = *reinterpret_cast<const ulonglong2*>(&s.vs[j][o0]);
#pragma unroll
                for (int a = 0; a < 4; a++) {
                    ull ap = pack2(s.sc[i0 + a][j]);
                    hacc[a][0] = fma2(ap, vv.x, hacc[a][0]);
                    hacc[a][1] = fma2(ap, vv.y, hacc[a][1]);
                }
            }
            ulonglong2 ewv = *reinterpret_cast<const ulonglong2*>(&s.ewsh[o0]);
#pragma unroll
            for (int a = 0; a < 4; a++) {
                ull ep = pack2(s.ec[i0 + a]);
                hacc[a][0] = fma2(ep, ewv.x, hacc[a][0]);
                hacc[a][1] = fma2(ep, ewv.y, hacc[a][1]);
            }
        }
        __syncthreads();  // S5: protect buffers for next head
    }

    // ---- final: mean heads + skip + bias, threshold, sigmoid ----
    if (tid < 256) {
        float4 bsv = *reinterpret_cast<const float4*>(&bs[o0]);
        const float bb[4] = {bsv.x, bsv.y, bsv.z, bsv.w};
#pragma unroll
        for (int a = 0; a < 4; a++) {
            float4 sk = *reinterpret_cast<const float4*>(&s.skips[i0 + a][o0]);
            float2 h0 = unpack2(hacc[a][0]), h1 = unpack2(hacc[a][1]);
            float z0 = sk.x + h0.x * 0.125f + bb[0];
            float z1 = sk.y + h0.y * 0.125f + bb[1];
            float z2 = sk.z + h1.x * 0.125f + bb[2];
            float z3 = sk.w + h1.y * 0.125f + bb[3];
            float4 res;
            res.x = (z0 > 0.1f) ? 1.0f / (1.0f + __expf(-z0)) : 0.0f;
            res.y = (z1 > 0.1f) ? 1.0f / (1.0f + __expf(-z1)) : 0.0f;
            res.z = (z2 > 0.1f) ? 1.0f / (1.0f + __expf(-z2)) : 0.0f;
            res.w = (z3 > 0.1f) ? 1.0f / (1.0f + __expf(-z3)) : 0.0f;
            *reinterpret_cast<float4*>(&s.sc[i0 + a][o0]) = res;
        }
    }
    __syncthreads();
    {
        float4* og = reinterpret_cast<float4*>(outg + (size_t)b * Nn * On);
        for (int p = tid; p < 1024; p += THREADS) {
            int i = p >> 4, g4 = p & 15;
            og[p] = *reinterpret_cast<const float4*>(&s.sc[i][g4 * 4]);
        }
    }
}

extern "C" void kernel_launch(void* const* d_in, const int* in_sizes, int n_in,
                              void* d_out, int out_size) {
    (void)in_sizes; (void)n_in; (void)out_size;
    const float* ctx = (const float*)d_in[0];
    const float* adj = (const float*)d_in[1];
    const float* Wq  = (const float*)d_in[2];
    const float* bq  = (const float*)d_in[3];
    const float* Wk  = (const float*)d_in[4];
    const float* bk  = (const float*)d_in[5];
    const float* Wv  = (const float*)d_in[6];
    const float* bv  = (const float*)d_in[7];
    const float* We  = (const float*)d_in[8];
    const float* Ws  = (const float*)d_in[9];
    const float* bs  = (const float*)d_in[10];
    float* outg = (float*)d_out;

    transpose_weights_kernel<<<(Cn * HOn + 255) / 256, 256>>>(Wq, Wk, Wv, Ws);

    cudaFuncSetAttribute(graph_attn_kernel,
                         cudaFuncAttributeMaxDynamicSharedMemorySize,
                         (int)sizeof(Smem));

    graph_attn_kernel<<<Bn, THREADS, sizeof(Smem)>>>(ctx, adj, bq, bk, bv, We, bs, outg);
}